// round 8
// baseline (speedup 1.0000x reference)
#include <cuda_runtime.h>
#include <cstdint>

#define B_  8
#define S_  512
#define E_  128
#define H_  512
#define BS_ (B_ * S_)      // 4096
#define O_  (E_ * E_)      // 16384
#define NCHUNK 4
#define SCH   (S_ / NCHUNK)   // 128 steps per chunk

// Persistent scratch (static __device__ — no runtime allocation)
__device__ float g_hidden[BS_ * H_];                 // 8 MB   [bs][h]
__device__ float g_Wa[(size_t)BS_ * O_];             // 268 MB [bs][o], o = d*128+e
__device__ float g_et[B_ * E_];                      // et carried across chunks

// ---------------------------------------------------------------------------
// XLA/Eigen fast tanh for f32 — exact coefficients and op order (bit-critical)
// ---------------------------------------------------------------------------
__device__ __forceinline__ float tanh_xla(float x) {
    const float kClamp = 7.90531110763549805f;
    float ax = fabsf(x);
    float xc = fmaxf(-kClamp, fminf(kClamp, x));
    float x2 = xc * xc;
    float p = fmaf(x2, -2.76076847742355e-16f, 2.00018790482477e-13f);
    p = fmaf(x2, p, -8.60467152213735e-11f);
    p = fmaf(x2, p,  5.12229709037114e-08f);
    p = fmaf(x2, p,  1.48572235717979e-05f);
    p = fmaf(x2, p,  6.37261928875436e-04f);
    p = fmaf(x2, p,  4.89352455891786e-03f);
    p = xc * p;
    float q = fmaf(x2, 1.19825839466702e-06f, 1.18534705686654e-04f);
    q = fmaf(x2, q, 2.26843463243900e-03f);
    q = fmaf(x2, q, 4.89352518554385e-03f);
    float r = p / q;
    return (ax < 0.0004f) ? x : r;
}

// ---------------------------------------------------------------------------
// packed f32x2 helpers (bitwise: IEEE fma per 32-bit half; pairing is across
// two DIFFERENT outputs — each output's chain stays one sequential chain)
// ---------------------------------------------------------------------------
__device__ __forceinline__ void ffma2_(unsigned long long& d,
                                       unsigned long long a,
                                       unsigned long long b) {
    asm("fma.rn.f32x2 %0, %1, %2, %0;" : "+l"(d) : "l"(a), "l"(b));
}
__device__ __forceinline__ unsigned long long dupf_(float x) {
    unsigned long long r;
    unsigned u = __float_as_uint(x);
    asm("mov.b64 %0, {%1, %1};" : "=l"(r) : "r"(u));
    return r;
}
__device__ __forceinline__ float lo_(unsigned long long a) {
    return __uint_as_float((unsigned)(a & 0xffffffffull));
}
__device__ __forceinline__ float hi_(unsigned long long a) {
    return __uint_as_float((unsigned)(a >> 32));
}

// ---------------------------------------------------------------------------
// async-copy / mbarrier helpers
// ---------------------------------------------------------------------------
__device__ __forceinline__ void cp_async16_(uint32_t dst, const void* src) {
    asm volatile("cp.async.cg.shared.global [%0], [%1], 16;"
                 :: "r"(dst), "l"(src) : "memory");
}
__device__ __forceinline__ void cp_commit_() {
    asm volatile("cp.async.commit_group;" ::: "memory");
}
__device__ __forceinline__ void cp_wait0_() {
    asm volatile("cp.async.wait_group 0;" ::: "memory");
}
__device__ __forceinline__ void mbar_init_(uint32_t a, uint32_t cnt) {
    asm volatile("mbarrier.init.shared.b64 [%0], %1;" :: "r"(a), "r"(cnt) : "memory");
}
__device__ __forceinline__ void mbar_expect_tx_(uint32_t a, uint32_t bytes) {
    asm volatile("mbarrier.arrive.expect_tx.shared.b64 _, [%0], %1;"
                 :: "r"(a), "r"(bytes) : "memory");
}
__device__ __forceinline__ void bulk_g2s_(uint32_t dst, const void* src,
                                          uint32_t bytes, uint32_t mbar) {
    asm volatile("cp.async.bulk.shared::cluster.global.mbarrier::complete_tx::bytes "
                 "[%0], [%1], %2, [%3];"
                 :: "r"(dst), "l"(src), "r"(bytes), "r"(mbar) : "memory");
}
__device__ __forceinline__ void mbar_wait_(uint32_t a, uint32_t parity) {
    asm volatile(
        "{\n\t.reg .pred P;\n\t"
        "WL%=:\n\t"
        "mbarrier.try_wait.parity.acquire.cta.shared::cta.b64 P, [%0], %1, 0x989680;\n\t"
        "@P bra WD%=;\n\t"
        "bra WL%=;\n\t"
        "WD%=:\n\t}"
        :: "r"(a), "r"(parity) : "memory");
}

// ---------------------------------------------------------------------------
// Kernel 1: hidden (unchanged — 55us)
// ---------------------------------------------------------------------------
#define HROWS 32
#define XPAD  36

__global__ void __launch_bounds__(512, 1)
hidden_kernel(const float* __restrict__ X,
              const float* __restrict__ W1,
              const float* __restrict__ b1) {
    extern __shared__ float sh[];
    float* x_s = sh;                    // [E_][XPAD]
    float* w1t = sh + E_ * XPAD;        // [32][512]

    const int row0 = blockIdx.x * HROWS;
    const int t    = threadIdx.x;       // h = t

    {
        const int r  = t & 31;
        const int e0 = (t >> 5) * 8;
        const float* src = X + (size_t)(row0 + r) * E_ + e0;
        float4 a = *(const float4*)src;
        float4 c = *(const float4*)(src + 4);
        x_s[(e0 + 0) * XPAD + r] = a.x; x_s[(e0 + 1) * XPAD + r] = a.y;
        x_s[(e0 + 2) * XPAD + r] = a.z; x_s[(e0 + 3) * XPAD + r] = a.w;
        x_s[(e0 + 4) * XPAD + r] = c.x; x_s[(e0 + 5) * XPAD + r] = c.y;
        x_s[(e0 + 6) * XPAD + r] = c.z; x_s[(e0 + 7) * XPAD + r] = c.w;
    }

    float acc[HROWS];
#pragma unroll
    for (int r = 0; r < HROWS; r++) acc[r] = 0.f;

    float4 w4[8];
    {
        const float* wsrc = W1 + (size_t)t * E_;
#pragma unroll
        for (int v = 0; v < 8; v++) w4[v] = ((const float4*)wsrc)[v];
    }

    for (int ec = 0; ec < E_; ec += 32) {
        __syncthreads();
#pragma unroll
        for (int v = 0; v < 8; v++) {
            w1t[(v * 4 + 0) * 512 + t] = w4[v].x;
            w1t[(v * 4 + 1) * 512 + t] = w4[v].y;
            w1t[(v * 4 + 2) * 512 + t] = w4[v].z;
            w1t[(v * 4 + 3) * 512 + t] = w4[v].w;
        }
        __syncthreads();
        if (ec + 32 < E_) {
            const float* wsrc = W1 + (size_t)t * E_ + ec + 32;
#pragma unroll
            for (int v = 0; v < 8; v++) w4[v] = ((const float4*)wsrc)[v];
        }
#pragma unroll 4
        for (int de = 0; de < 32; de++) {      // e ascending — order-critical
            float wv = w1t[de * 512 + t];
            const float* xrow = x_s + (ec + de) * XPAD;
#pragma unroll
            for (int j = 0; j < 8; j++) {
                float4 xv = *(const float4*)(xrow + 4 * j);
                acc[4 * j + 0] = fmaf(xv.x, wv, acc[4 * j + 0]);
                acc[4 * j + 1] = fmaf(xv.y, wv, acc[4 * j + 1]);
                acc[4 * j + 2] = fmaf(xv.z, wv, acc[4 * j + 2]);
                acc[4 * j + 3] = fmaf(xv.w, wv, acc[4 * j + 3]);
            }
        }
    }

    const float bias = b1[t];
#pragma unroll 4
    for (int r = 0; r < HROWS; r++)
        g_hidden[(size_t)(row0 + r) * H_ + t] = tanh_xla(acc[r] + bias);
}

#define HID_SMEM ((E_ * XPAD + 32 * 512) * 4)   // 83968 bytes

// ---------------------------------------------------------------------------
// Kernel 2 (chunked): Wa[bs][o] = (seq-h FFMA2 chain) + b2[o]
// Retiled: per-thread 16 o (8 pairs, FFMA2-paired) x 4 bs (dup side).
//   to = tid&7  -> o pairs o0 = 2*to + 16*i, i=0..7
//   tb = tid>>3 -> bs rows bs = tb + 32*j,   j=0..3
// w tile: register-transposed ping-pong smem [k][o] (LDS.64, bcast x4, no conflict)
// h tile: cp.async ping-pong smem [bs][36] padded (bank = 4*tb+k, conflict-free)
// Accumulation: k strictly ascending, one chain per output — order-critical.
// ---------------------------------------------------------------------------
#define BO   128
#define KC   32
#define HPAD 36
#define NT   (H_ / KC)   // 16 tiles

__global__ void __launch_bounds__(256, 2)
wa_kernel(const float* __restrict__ W2, const float* __restrict__ b2, int chunk) {
    __shared__ __align__(16) float w_s[2][KC][BO];     // 2 x 16 KB, [k][o]
    __shared__ __align__(16) float h_s[2][BO][HPAD];   // 2 x 18 KB, [bs][k] padded

    const int obase  = blockIdx.x * BO;
    const int bsbase = blockIdx.y * S_ + chunk * SCH;   // b = blockIdx.y
    const int tid    = threadIdx.x;
    const int to = tid & 7;      // o-pair group
    const int tb = tid >> 3;     // bs group 0..31

    // accp[j][i]: packed pair (o0, o0+1) accumulator for bs = tb + 32*j
    unsigned long long accp[4][8];
#pragma unroll
    for (int j = 0; j < 4; j++)
#pragma unroll
        for (int i = 0; i < 8; i++) accp[j][i] = 0ull;

    const int r   = tid >> 1;          // w-tile row 0..127
    const int seg = (tid & 1) * 16;    // 16 k-values per thread (w staging)

    const float*    wsrc0   = W2 + (size_t)(obase + r) * H_ + seg;
    const uint32_t  h_smem0 = (uint32_t)__cvta_generic_to_shared(&h_s[0][0][0]);

    // h cp.async: 128 rows x 32 floats = 1024 16B chunks per tile, 4/thread
    auto stage_h = [&](int buf, int kc) {
#pragma unroll
        for (int q = 0; q < 4; q++) {
            int id   = q * 256 + tid;
            int row  = id >> 3;            // 0..127
            int c16  = (id & 7) * 4;       // float offset within row
            const float* src = g_hidden + (size_t)(bsbase + row) * H_ + kc + c16;
            uint32_t dst = h_smem0 + ((buf * BO + row) * HPAD + c16) * 4;
            cp_async16_(dst, src);
        }
        cp_commit_();
    };

    // prologue: tile 0
    stage_h(0, 0);
    float4 wreg[4];
#pragma unroll
    for (int v = 0; v < 4; v++) wreg[v] = *(const float4*)(wsrc0 + v * 4);

    for (int it = 0; it < NT; it++) {
        const int cur = it & 1;
        // store w tile it (transposed)
#pragma unroll
        for (int v = 0; v < 4; v++) {
            w_s[cur][seg + v * 4 + 0][r] = wreg[v].x;
            w_s[cur][seg + v * 4 + 1][r] = wreg[v].y;
            w_s[cur][seg + v * 4 + 2][r] = wreg[v].z;
            w_s[cur][seg + v * 4 + 3][r] = wreg[v].w;
        }
        cp_wait0_();              // h tile 'it' copies done
        __syncthreads();          // everyone's h + w visible; prev bufs free

        if (it + 1 < NT) {        // prefetch next tile under the k-loop
            stage_h(cur ^ 1, (it + 1) * KC);
#pragma unroll
            for (int v = 0; v < 4; v++)
                wreg[v] = *(const float4*)(wsrc0 + (it + 1) * KC + v * 4);
        }

#pragma unroll 8
        for (int k = 0; k < KC; k++) {   // k strictly ascending — order-critical
            unsigned long long wv2[8];
#pragma unroll
            for (int i = 0; i < 8; i++)
                wv2[i] = *(const unsigned long long*)&w_s[cur][k][2 * to + 16 * i];
            unsigned long long dl[4];
#pragma unroll
            for (int j = 0; j < 4; j++)
                dl[j] = dupf_(h_s[cur][tb + 32 * j][k]);
#pragma unroll
            for (int j = 0; j < 4; j++)
#pragma unroll
                for (int i = 0; i < 8; i++)
                    ffma2_(accp[j][i], wv2[i], dl[j]);
        }
    }

    // epilogue: + b2, float2 stores
#pragma unroll
    for (int i = 0; i < 8; i++) {
        int o0 = obase + 2 * to + 16 * i;
        float2 bb = *(const float2*)&b2[o0];
#pragma unroll
        for (int j = 0; j < 4; j++) {
            int bs = bsbase + tb + 32 * j;
            unsigned long long a = accp[j][i];
            float2 res = make_float2(lo_(a) + bb.x, hi_(a) + bb.y);
            *(float2*)&g_Wa[(size_t)bs * O_ + o0] = res;
        }
    }
}

// ---------------------------------------------------------------------------
// Kernel 3 (chunked): recurrence steps s in [max(1,chunk*128), chunk*128+128).
// Triple-buffered TMA prefetch; et carried via g_et across chunks (exact copy).
// Arithmetic identical: seq-d FMA chain from smem, clip.
// ---------------------------------------------------------------------------
#define STAGES 3
#define TILE_BYTES_R (O_ * 4)   // 65536

__global__ void __launch_bounds__(E_, 1)
recur_kernel(const float* __restrict__ e0, float* __restrict__ out, int chunk) {
    extern __shared__ float wa_buf[];            // STAGES * O_ floats (192 KB)
    __shared__ float et_s[E_];
    __shared__ __align__(8) unsigned long long mbar[STAGES];

    const int b = blockIdx.x;      // 0..7
    const int e = threadIdx.x;     // 0..127

    uint32_t mb[STAGES];
#pragma unroll
    for (int i = 0; i < STAGES; i++)
        mb[i] = (uint32_t)__cvta_generic_to_shared(&mbar[i]);

    if (e == 0) {
#pragma unroll
        for (int i = 0; i < STAGES; i++) mbar_init_(mb[i], 1);
    }

    const int s_begin = (chunk == 0) ? 1 : chunk * SCH;
    const int s_end   = chunk * SCH + SCH;

    float v;
    if (chunk == 0) {
        v = e0[e];
        out[((size_t)b * S_ + 0) * E_ + e] = v;
    } else {
        v = g_et[b * E_ + e];
    }
    et_s[e] = v;
    __syncthreads();   // mbar init + et_s visible

    const float* wa_base = g_Wa + (size_t)b * S_ * O_;

    if (e == 0) {
#pragma unroll
        for (int i = 0; i < STAGES; i++) {
            if (s_begin + i < s_end) {
                mbar_expect_tx_(mb[i], TILE_BYTES_R);
                bulk_g2s_((uint32_t)__cvta_generic_to_shared(&wa_buf[i * O_]),
                          wa_base + (size_t)(s_begin + i) * O_, TILE_BYTES_R, mb[i]);
            }
        }
    }

    for (int s = s_begin; s < s_end; s++) {
        const int      i      = s - s_begin;
        const int      slot   = i % STAGES;
        const uint32_t parity = (uint32_t)((i / STAGES) & 1);
        mbar_wait_(mb[slot], parity);

        const float* buf = wa_buf + slot * O_;
        float acc = 0.f;
#pragma unroll 16
        for (int d = 0; d < E_; d++)           // d ascending — order-critical
            acc = fmaf(et_s[d], buf[d * E_ + e], acc);
        float nv = fminf(5.0f, fmaxf(-5.0f, acc));
        out[((size_t)b * S_ + s) * E_ + e] = nv;

        __syncthreads();                       // all done reading buf & et_s
        et_s[e] = nv;
        if (e == 0 && s + STAGES < s_end) {
            mbar_expect_tx_(mb[slot], TILE_BYTES_R);
            bulk_g2s_((uint32_t)__cvta_generic_to_shared(&wa_buf[slot * O_]),
                      wa_base + (size_t)(s + STAGES) * O_, TILE_BYTES_R, mb[slot]);
        }
        __syncthreads();                       // et_s published
        v = nv;
    }

    g_et[b * E_ + e] = v;                      // exact fp32 pass-through
}

// ---------------------------------------------------------------------------
// Launch: wa chunks on TWO alternating streams (mutually independent) so each
// chunk's partial last wave overlaps the next chunk's first wave. recur chunks
// chained on a third stream, gated per-chunk on the matching wa event.
// Streams/events created once in the first (uncaptured) correctness call.
// ---------------------------------------------------------------------------
extern "C" void kernel_launch(void* const* d_in, const int* in_sizes, int n_in,
                              void* d_out, int out_size) {
    const float* X  = (const float*)d_in[0];   // [8,512,128]
    const float* W1 = (const float*)d_in[1];   // [512,128]
    const float* b1 = (const float*)d_in[2];   // [512]
    const float* W2 = (const float*)d_in[3];   // [16384,512]
    const float* b2 = (const float*)d_in[4];   // [16384]
    const float* e0 = (const float*)d_in[5];   // [1,128]
    float* out = (float*)d_out;                // [8,512,128] float32

    static cudaStream_t sW[2] = {nullptr, nullptr};
    static cudaStream_t sR = nullptr;
    static cudaEvent_t  ev_hid;
    static cudaEvent_t  ev_wa[NCHUNK];
    static cudaEvent_t  ev_join;
    if (sR == nullptr) {
        cudaStreamCreateWithFlags(&sW[0], cudaStreamNonBlocking);
        cudaStreamCreateWithFlags(&sW[1], cudaStreamNonBlocking);
        cudaStreamCreateWithFlags(&sR, cudaStreamNonBlocking);
        cudaEventCreateWithFlags(&ev_hid, cudaEventDisableTiming);
        for (int c = 0; c < NCHUNK; c++)
            cudaEventCreateWithFlags(&ev_wa[c], cudaEventDisableTiming);
        cudaEventCreateWithFlags(&ev_join, cudaEventDisableTiming);
        cudaFuncSetAttribute(hidden_kernel,
                             cudaFuncAttributeMaxDynamicSharedMemorySize, HID_SMEM);
        cudaFuncSetAttribute(recur_kernel,
                             cudaFuncAttributeMaxDynamicSharedMemorySize,
                             STAGES * TILE_BYTES_R);
    }

    hidden_kernel<<<BS_ / HROWS, 512, HID_SMEM>>>(X, W1, b1);
    cudaEventRecord(ev_hid, 0);

    dim3 gridW(O_ / BO, B_);   // 128 o-tiles x 8 batches per chunk
    for (int c = 0; c < NCHUNK; c++) {
        cudaStream_t ws = sW[c & 1];
        cudaStreamWaitEvent(ws, ev_hid, 0);
        wa_kernel<<<gridW, 256, 0, ws>>>(W2, b2, c);
        cudaEventRecord(ev_wa[c], ws);
    }
    for (int c = 0; c < NCHUNK; c++) {
        cudaStreamWaitEvent(sR, ev_wa[c], 0);
        recur_kernel<<<B_, E_, STAGES * TILE_BYTES_R, sR>>>(e0, out, c);
    }
    cudaEventRecord(ev_join, sR);
    cudaStreamWaitEvent(0, ev_join, 0);
}